// round 7
// baseline (speedup 1.0000x reference)
#include <cuda_runtime.h>

// ---------------------------------------------------------------------------
// ANODE Dopri5 solve, persistent per-block kernel.
// ts[128], y0[2048,128], W1[256,128], b1[256], W2[256,256], b2[256],
// W3[128,256], b3[128]  ->  ys[128,2048,64] (+ num_steps scalar tail)
// ---------------------------------------------------------------------------

#define T_STEPS  128
#define SUBSTEPS 4
#define BATCH    2048
#define DIM      128
#define WIDTH    256
#define DATA     64

#define M_TILE   14
#define GRID_X   147          // 147*14 = 2058 >= 2048
#define NTHREADS 256

typedef unsigned long long ull;

// Transposed + float4-packed weights (filled by prep kernel each call).
// Layout: Wt[kq][o] = {W[o][4kq+0..3]}  -> coalesced LDG.128 across o.
__device__ float4 g_W1t[32 * 256];   // 128 KB
__device__ float4 g_W2t[64 * 256];   // 256 KB
__device__ float4 g_W3t[64 * 128];   // 128 KB

__device__ __forceinline__ void fma2(ull& d, ull a, ull b) {
    asm("fma.rn.f32x2 %0, %1, %2, %0;" : "+l"(d) : "l"(a), "l"(b));
}
__device__ __forceinline__ float hsum2(ull v) {
    float lo, hi;
    asm("mov.b64 {%0,%1}, %2;" : "=f"(lo), "=f"(hi) : "l"(v));
    return lo + hi;
}

// Dynamic shared memory layout (float offsets, all 16B aligned)
#define OFF_YS   0                    // [M_TILE][128]
#define OFF_YT   1792                 // [M_TILE][128]
#define OFF_K    3584                 // 6 x [M_TILE][128]
#define OFF_HA   14336                // [M_TILE][256]
#define OFF_HB   17920                // [M_TILE][256]
#define OFF_RED  21504                // [M_TILE][128]
#define OFF_B1   23296
#define OFF_B2   23552
#define OFF_B3   23808
#define SMEM_FLOATS 23936             // 95744 bytes

// ---------------------------------------------------------------------------
// f(y) = W3 @ relu(W2 @ relu(W1 @ y + b1) + b2) + b3   for M_TILE rows.
// Yin, Kout are smem [M_TILE][128].
// ---------------------------------------------------------------------------
__device__ __noinline__ void f_eval(const float* __restrict__ Yin,
                                    float* __restrict__ Kout) {
    extern __shared__ float sm[];
    const int tid = threadIdx.x;
    float* Ha  = sm + OFF_HA;
    float* Hb  = sm + OFF_HB;
    float* Red = sm + OFF_RED;

    // ---- Layer 1: [M,128] -> [M,256], thread = output channel ----
    {
        ull acc[M_TILE];
#pragma unroll
        for (int m = 0; m < M_TILE; m++) acc[m] = 0ull;
        const ulonglong2* wp = reinterpret_cast<const ulonglong2*>(g_W1t) + tid;
#pragma unroll 4
        for (int kq = 0; kq < 32; kq++) {
            ulonglong2 w = wp[kq * 256];
#pragma unroll
            for (int m = 0; m < M_TILE; m++) {
                ulonglong2 yv =
                    *reinterpret_cast<const ulonglong2*>(Yin + m * DIM + kq * 4);
                fma2(acc[m], w.x, yv.x);
                fma2(acc[m], w.y, yv.y);
            }
        }
        const float b = sm[OFF_B1 + tid];
#pragma unroll
        for (int m = 0; m < M_TILE; m++) {
            float v = hsum2(acc[m]) + b;
            Ha[m * WIDTH + tid] = v > 0.f ? v : 0.f;
        }
    }
    __syncthreads();

    // ---- Layer 2: [M,256] -> [M,256] ----
    {
        ull acc[M_TILE];
#pragma unroll
        for (int m = 0; m < M_TILE; m++) acc[m] = 0ull;
        const ulonglong2* wp = reinterpret_cast<const ulonglong2*>(g_W2t) + tid;
#pragma unroll 4
        for (int kq = 0; kq < 64; kq++) {
            ulonglong2 w = wp[kq * 256];
#pragma unroll
            for (int m = 0; m < M_TILE; m++) {
                ulonglong2 yv =
                    *reinterpret_cast<const ulonglong2*>(Ha + m * WIDTH + kq * 4);
                fma2(acc[m], w.x, yv.x);
                fma2(acc[m], w.y, yv.y);
            }
        }
        const float b = sm[OFF_B2 + tid];
#pragma unroll
        for (int m = 0; m < M_TILE; m++) {
            float v = hsum2(acc[m]) + b;
            Hb[m * WIDTH + tid] = v > 0.f ? v : 0.f;
        }
    }
    __syncthreads();

    // ---- Layer 3: [M,256] -> [M,128], split-K over 2 thread halves ----
    {
        const int o  = tid & 127;
        const int kh = tid >> 7;
        const int kq0 = kh * 32;
        ull acc[M_TILE];
#pragma unroll
        for (int m = 0; m < M_TILE; m++) acc[m] = 0ull;
        const ulonglong2* wp = reinterpret_cast<const ulonglong2*>(g_W3t) + o;
#pragma unroll 4
        for (int kq = 0; kq < 32; kq++) {
            ulonglong2 w = wp[(kq0 + kq) * 128];
#pragma unroll
            for (int m = 0; m < M_TILE; m++) {
                ulonglong2 yv = *reinterpret_cast<const ulonglong2*>(
                    Hb + m * WIDTH + (kq0 + kq) * 4);
                fma2(acc[m], w.x, yv.x);
                fma2(acc[m], w.y, yv.y);
            }
        }
        if (kh) {
#pragma unroll
            for (int m = 0; m < M_TILE; m++) Red[m * DIM + o] = hsum2(acc[m]);
        }
        __syncthreads();
        if (!kh) {
            const float b = sm[OFF_B3 + o];
#pragma unroll
            for (int m = 0; m < M_TILE; m++)
                Kout[m * DIM + o] = hsum2(acc[m]) + Red[m * DIM + o] + b;
        }
    }
    __syncthreads();
}

// ---------------------------------------------------------------------------
__global__ __launch_bounds__(NTHREADS, 1)
void anode_main(const float* __restrict__ ts, const float* __restrict__ y0,
                const float* __restrict__ b1, const float* __restrict__ b2,
                const float* __restrict__ b3, float* __restrict__ out,
                int out_size) {
    extern __shared__ float sm[];
    const int tid  = threadIdx.x;
    const int base = blockIdx.x * M_TILE;

    float* Ys = sm + OFF_YS;
    float* Yt = sm + OFF_YT;
    float* K1 = sm + OFF_K;
    float* K2 = K1 + 1792;
    float* K3 = K2 + 1792;
    float* K4 = K3 + 1792;
    float* K5 = K4 + 1792;
    float* K6 = K5 + 1792;

    // biases -> smem
    sm[OFF_B1 + tid] = b1[tid];
    sm[OFF_B2 + tid] = b2[tid];
    if (tid < 128) sm[OFF_B3 + tid] = b3[tid];

    // load y0 rows (zero-pad past BATCH)
    for (int i = tid; i < M_TILE * DIM; i += NTHREADS) {
        int m = i >> 7, d = i & 127;
        int row = base + m;
        Ys[i] = (row < BATCH) ? y0[(size_t)row * DIM + d] : 0.f;
    }
    __syncthreads();

    // save t = 0
    for (int i = tid; i < M_TILE * DATA; i += NTHREADS) {
        int m = i / DATA, c = i % DATA;
        int row = base + m;
        if (row < BATCH) out[(size_t)row * DATA + c] = Ys[m * DIM + c];
    }

    const int NE = M_TILE * DIM;

    for (int ti = 0; ti < T_STEPS - 1; ti++) {
        const float dt = (ts[ti + 1] - ts[ti]) * (1.0f / SUBSTEPS);

        for (int sub = 0; sub < SUBSTEPS; sub++) {
            f_eval(Ys, K1);
            for (int i = tid; i < NE; i += NTHREADS)
                Yt[i] = fmaf(dt, 0.2f * K1[i], Ys[i]);
            __syncthreads();

            f_eval(Yt, K2);
            for (int i = tid; i < NE; i += NTHREADS) {
                float s = (float)(3.0 / 40.0) * K1[i] + (float)(9.0 / 40.0) * K2[i];
                Yt[i] = fmaf(dt, s, Ys[i]);
            }
            __syncthreads();

            f_eval(Yt, K3);
            for (int i = tid; i < NE; i += NTHREADS) {
                float s = (float)(44.0 / 45.0) * K1[i]
                        + (float)(-56.0 / 15.0) * K2[i]
                        + (float)(32.0 / 9.0)   * K3[i];
                Yt[i] = fmaf(dt, s, Ys[i]);
            }
            __syncthreads();

            f_eval(Yt, K4);
            for (int i = tid; i < NE; i += NTHREADS) {
                float s = (float)(19372.0 / 6561.0)  * K1[i]
                        + (float)(-25360.0 / 2187.0) * K2[i]
                        + (float)(64448.0 / 6561.0)  * K3[i]
                        + (float)(-212.0 / 729.0)    * K4[i];
                Yt[i] = fmaf(dt, s, Ys[i]);
            }
            __syncthreads();

            f_eval(Yt, K5);
            for (int i = tid; i < NE; i += NTHREADS) {
                float s = (float)(9017.0 / 3168.0)    * K1[i]
                        + (float)(-355.0 / 33.0)      * K2[i]
                        + (float)(46732.0 / 5247.0)   * K3[i]
                        + (float)(49.0 / 176.0)       * K4[i]
                        + (float)(-5103.0 / 18656.0)  * K5[i];
                Yt[i] = fmaf(dt, s, Ys[i]);
            }
            __syncthreads();

            f_eval(Yt, K6);
            for (int i = tid; i < NE; i += NTHREADS) {
                float s = (float)(35.0 / 384.0)      * K1[i]
                        + (float)(500.0 / 1113.0)    * K3[i]
                        + (float)(125.0 / 192.0)     * K4[i]
                        + (float)(-2187.0 / 6784.0)  * K5[i]
                        + (float)(11.0 / 84.0)       * K6[i];
                Ys[i] = fmaf(dt, s, Ys[i]);
            }
            __syncthreads();
        }

        // save t = ti+1
        float* outp = out + (size_t)(ti + 1) * BATCH * DATA;
        for (int i = tid; i < M_TILE * DATA; i += NTHREADS) {
            int m = i / DATA, c = i % DATA;
            int row = base + m;
            if (row < BATCH) outp[(size_t)row * DATA + c] = Ys[m * DIM + c];
        }
    }

    // num_steps tail element (tuple second leaf), if the harness expects it
    if (blockIdx.x == 0 && tid == 0) {
        long long ysz = (long long)T_STEPS * BATCH * DATA;
        if (out_size > ysz) out[ysz] = (float)((T_STEPS - 1) * SUBSTEPS);
    }
}

// ---------------------------------------------------------------------------
// Weight transpose + float4 pack (runs inside the graph each call; cheap).
// ---------------------------------------------------------------------------
__global__ void prep_kernel(const float* __restrict__ W1,
                            const float* __restrict__ W2,
                            const float* __restrict__ W3) {
    int i = blockIdx.x * blockDim.x + threadIdx.x;
    if (i < 32 * 256) {                     // W1: [256,128] -> [32][256] float4
        int kq = i >> 8, o = i & 255;
        const float* s = W1 + o * 128 + kq * 4;
        g_W1t[i] = make_float4(s[0], s[1], s[2], s[3]);
    } else if (i < 32 * 256 + 64 * 256) {   // W2: [256,256] -> [64][256]
        int j = i - 32 * 256;
        int kq = j >> 8, o = j & 255;
        const float* s = W2 + o * 256 + kq * 4;
        g_W2t[j] = make_float4(s[0], s[1], s[2], s[3]);
    } else {                                // W3: [128,256] -> [64][128]
        int j = i - (32 * 256 + 64 * 256);
        int kq = j >> 7, o = j & 127;
        const float* s = W3 + o * 256 + kq * 4;
        g_W3t[j] = make_float4(s[0], s[1], s[2], s[3]);
    }
}

// ---------------------------------------------------------------------------
extern "C" void kernel_launch(void* const* d_in, const int* in_sizes, int n_in,
                              void* d_out, int out_size) {
    (void)in_sizes; (void)n_in;
    const float* ts = (const float*)d_in[0];
    const float* y0 = (const float*)d_in[1];
    const float* W1 = (const float*)d_in[2];
    const float* b1 = (const float*)d_in[3];
    const float* W2 = (const float*)d_in[4];
    const float* b2 = (const float*)d_in[5];
    const float* W3 = (const float*)d_in[6];
    const float* b3 = (const float*)d_in[7];
    float* out = (float*)d_out;

    // 32768 float4 elements total
    prep_kernel<<<128, 256>>>(W1, W2, W3);

    const int smem_bytes = SMEM_FLOATS * (int)sizeof(float);
    cudaFuncSetAttribute(anode_main,
                         cudaFuncAttributeMaxDynamicSharedMemorySize, smem_bytes);
    anode_main<<<GRID_X, NTHREADS, smem_bytes>>>(ts, y0, b1, b2, b3, out,
                                                 out_size);
}

// round 8
// speedup vs baseline: 1.2678x; 1.2678x over previous
#include <cuda_runtime.h>

// ---------------------------------------------------------------------------
// ANODE Dopri5 solve, persistent per-block kernel. Round 8:
//   512 threads/block, 2 output channels per thread, split-K with smem
//   reduction. FFMA2 (fma.rn.f32x2) throughout, pure fp32 math.
// ---------------------------------------------------------------------------

#define T_STEPS  128
#define SUBSTEPS 4
#define BATCH    2048
#define DIM      128
#define WIDTH    256
#define DATA     64

#define M_TILE   14
#define GRID_X   147          // 147*14 = 2058 >= 2048
#define NTHREADS 512

typedef unsigned long long ull;

// Transposed + float4-packed weights: Wt[kq][o] = {W[o][4kq+0..3]}
__device__ float4 g_W1t[32 * 256];   // 128 KB
__device__ float4 g_W2t[64 * 256];   // 256 KB
__device__ float4 g_W3t[64 * 128];   // 128 KB

__device__ __forceinline__ void fma2(ull& d, ull a, ull b) {
    asm("fma.rn.f32x2 %0, %1, %2, %0;" : "+l"(d) : "l"(a), "l"(b));
}
__device__ __forceinline__ float hsum2(ull v) {
    float lo, hi;
    asm("mov.b64 {%0,%1}, %2;" : "=f"(lo), "=f"(hi) : "l"(v));
    return lo + hi;
}

// Shared memory layout (float offsets; all 16B aligned)
#define OFF_YS   0                    // [14][128]
#define OFF_YT   1792                 // [14][128]
#define OFF_K    3584                 // 6 x [14][128]
#define OFF_HA   14336                // [14][256]
#define OFF_HB   17920                // [14][256]
#define OFF_RED  21504                // max(4*[14][256], 8*[14][128]) = 14336
#define OFF_B1   35840
#define OFF_B2   36096
#define OFF_B3   36352
#define SMEM_FLOATS 36480             // 145920 bytes

// ---------------------------------------------------------------------------
// f(y) = W3 @ relu(W2 @ relu(W1 @ y + b1) + b2) + b3  for M_TILE rows.
// ---------------------------------------------------------------------------
__device__ __noinline__ void f_eval(const float* __restrict__ Yin,
                                    float* __restrict__ Kout) {
    extern __shared__ float sm[];
    const int tid = threadIdx.x;
    float* Ha  = sm + OFF_HA;
    float* Hb  = sm + OFF_HB;
    float* Red = sm + OFF_RED;

    // ---- Layer 1: [14,128] -> [14,256]. 128 cols x 2ch, 4-way split-K ----
    {
        const int col = tid & 127;
        const int kh  = tid >> 7;            // 0..3
        ull a0[M_TILE], a1[M_TILE];
#pragma unroll
        for (int m = 0; m < M_TILE; m++) { a0[m] = 0ull; a1[m] = 0ull; }
        const ulonglong2* wp = reinterpret_cast<const ulonglong2*>(g_W1t) + col;
#pragma unroll
        for (int j = 0; j < 8; j++) {
            const int kq = kh * 8 + j;
            ulonglong2 w0 = wp[kq * 256];
            ulonglong2 w1 = wp[kq * 256 + 128];
#pragma unroll
            for (int m = 0; m < M_TILE; m++) {
                ulonglong2 yv =
                    *reinterpret_cast<const ulonglong2*>(Yin + m * DIM + kq * 4);
                fma2(a0[m], w0.x, yv.x); fma2(a0[m], w0.y, yv.y);
                fma2(a1[m], w1.x, yv.x); fma2(a1[m], w1.y, yv.y);
            }
        }
        float* r = Red + kh * (M_TILE * 256) + col;
#pragma unroll
        for (int m = 0; m < M_TILE; m++) {
            r[m * 256]       = hsum2(a0[m]);
            r[m * 256 + 128] = hsum2(a1[m]);
        }
        __syncthreads();
#pragma unroll
        for (int i = 0; i < 7; i++) {
            int out = tid + NTHREADS * i;          // < 3584
            int m = out >> 8, n = out & 255;
            int idx = m * 256 + n;
            float v = Red[idx] + Red[idx + 3584] + Red[idx + 7168]
                    + Red[idx + 10752] + sm[OFF_B1 + n];
            Ha[idx] = v > 0.f ? v : 0.f;
        }
        __syncthreads();
    }

    // ---- Layer 2: [14,256] -> [14,256]. 128 cols x 2ch, 4-way split-K ----
    {
        const int col = tid & 127;
        const int kh  = tid >> 7;
        ull a0[M_TILE], a1[M_TILE];
#pragma unroll
        for (int m = 0; m < M_TILE; m++) { a0[m] = 0ull; a1[m] = 0ull; }
        const ulonglong2* wp = reinterpret_cast<const ulonglong2*>(g_W2t) + col;
#pragma unroll 4
        for (int j = 0; j < 16; j++) {
            const int kq = kh * 16 + j;
            ulonglong2 w0 = wp[kq * 256];
            ulonglong2 w1 = wp[kq * 256 + 128];
#pragma unroll
            for (int m = 0; m < M_TILE; m++) {
                ulonglong2 yv =
                    *reinterpret_cast<const ulonglong2*>(Ha + m * WIDTH + kq * 4);
                fma2(a0[m], w0.x, yv.x); fma2(a0[m], w0.y, yv.y);
                fma2(a1[m], w1.x, yv.x); fma2(a1[m], w1.y, yv.y);
            }
        }
        float* r = Red + kh * (M_TILE * 256) + col;
#pragma unroll
        for (int m = 0; m < M_TILE; m++) {
            r[m * 256]       = hsum2(a0[m]);
            r[m * 256 + 128] = hsum2(a1[m]);
        }
        __syncthreads();
#pragma unroll
        for (int i = 0; i < 7; i++) {
            int out = tid + NTHREADS * i;
            int m = out >> 8, n = out & 255;
            int idx = m * 256 + n;
            float v = Red[idx] + Red[idx + 3584] + Red[idx + 7168]
                    + Red[idx + 10752] + sm[OFF_B2 + n];
            Hb[idx] = v > 0.f ? v : 0.f;
        }
        __syncthreads();
    }

    // ---- Layer 3: [14,256] -> [14,128]. 64 cols x 2ch, 8-way split-K ----
    {
        const int col = tid & 63;
        const int kh  = tid >> 6;            // 0..7
        ull a0[M_TILE], a1[M_TILE];
#pragma unroll
        for (int m = 0; m < M_TILE; m++) { a0[m] = 0ull; a1[m] = 0ull; }
        const ulonglong2* wp = reinterpret_cast<const ulonglong2*>(g_W3t) + col;
#pragma unroll
        for (int j = 0; j < 8; j++) {
            const int kq = kh * 8 + j;
            ulonglong2 w0 = wp[kq * 128];
            ulonglong2 w1 = wp[kq * 128 + 64];
#pragma unroll
            for (int m = 0; m < M_TILE; m++) {
                ulonglong2 yv =
                    *reinterpret_cast<const ulonglong2*>(Hb + m * WIDTH + kq * 4);
                fma2(a0[m], w0.x, yv.x); fma2(a0[m], w0.y, yv.y);
                fma2(a1[m], w1.x, yv.x); fma2(a1[m], w1.y, yv.y);
            }
        }
        float* r = Red + kh * (M_TILE * 128) + col;
#pragma unroll
        for (int m = 0; m < M_TILE; m++) {
            r[m * 128]      = hsum2(a0[m]);
            r[m * 128 + 64] = hsum2(a1[m]);
        }
        __syncthreads();
        for (int out = tid; out < M_TILE * 128; out += NTHREADS) {
            int m = out >> 7, n = out & 127;
            int idx = m * 128 + n;
            float v = sm[OFF_B3 + n];
#pragma unroll
            for (int p = 0; p < 8; p++) v += Red[idx + p * 1792];
            Kout[idx] = v;
        }
        __syncthreads();
    }
}

// ---------------------------------------------------------------------------
__global__ __launch_bounds__(NTHREADS, 1)
void anode_main(const float* __restrict__ ts, const float* __restrict__ y0,
                const float* __restrict__ b1, const float* __restrict__ b2,
                const float* __restrict__ b3, float* __restrict__ out,
                int out_size) {
    extern __shared__ float sm[];
    const int tid  = threadIdx.x;
    const int base = blockIdx.x * M_TILE;

    float* Ys = sm + OFF_YS;
    float* Yt = sm + OFF_YT;
    float* K1 = sm + OFF_K;
    float* K2 = K1 + 1792;
    float* K3 = K2 + 1792;
    float* K4 = K3 + 1792;
    float* K5 = K4 + 1792;
    float* K6 = K5 + 1792;

    if (tid < 256) { sm[OFF_B1 + tid] = b1[tid]; sm[OFF_B2 + tid] = b2[tid]; }
    if (tid < 128) sm[OFF_B3 + tid] = b3[tid];

    for (int i = tid; i < M_TILE * DIM; i += NTHREADS) {
        int m = i >> 7, d = i & 127;
        int row = base + m;
        Ys[i] = (row < BATCH) ? y0[(size_t)row * DIM + d] : 0.f;
    }
    __syncthreads();

    // save t = 0
    for (int i = tid; i < M_TILE * DATA; i += NTHREADS) {
        int m = i / DATA, c = i % DATA;
        int row = base + m;
        if (row < BATCH) out[(size_t)row * DATA + c] = Ys[m * DIM + c];
    }

    const int NE = M_TILE * DIM;

    for (int ti = 0; ti < T_STEPS - 1; ti++) {
        const float dt = (ts[ti + 1] - ts[ti]) * (1.0f / SUBSTEPS);

        for (int sub = 0; sub < SUBSTEPS; sub++) {
            f_eval(Ys, K1);
            for (int i = tid; i < NE; i += NTHREADS)
                Yt[i] = fmaf(dt, 0.2f * K1[i], Ys[i]);
            __syncthreads();

            f_eval(Yt, K2);
            for (int i = tid; i < NE; i += NTHREADS) {
                float s = (float)(3.0 / 40.0) * K1[i] + (float)(9.0 / 40.0) * K2[i];
                Yt[i] = fmaf(dt, s, Ys[i]);
            }
            __syncthreads();

            f_eval(Yt, K3);
            for (int i = tid; i < NE; i += NTHREADS) {
                float s = (float)(44.0 / 45.0) * K1[i]
                        + (float)(-56.0 / 15.0) * K2[i]
                        + (float)(32.0 / 9.0)   * K3[i];
                Yt[i] = fmaf(dt, s, Ys[i]);
            }
            __syncthreads();

            f_eval(Yt, K4);
            for (int i = tid; i < NE; i += NTHREADS) {
                float s = (float)(19372.0 / 6561.0)  * K1[i]
                        + (float)(-25360.0 / 2187.0) * K2[i]
                        + (float)(64448.0 / 6561.0)  * K3[i]
                        + (float)(-212.0 / 729.0)    * K4[i];
                Yt[i] = fmaf(dt, s, Ys[i]);
            }
            __syncthreads();

            f_eval(Yt, K5);
            for (int i = tid; i < NE; i += NTHREADS) {
                float s = (float)(9017.0 / 3168.0)    * K1[i]
                        + (float)(-355.0 / 33.0)      * K2[i]
                        + (float)(46732.0 / 5247.0)   * K3[i]
                        + (float)(49.0 / 176.0)       * K4[i]
                        + (float)(-5103.0 / 18656.0)  * K5[i];
                Yt[i] = fmaf(dt, s, Ys[i]);
            }
            __syncthreads();

            f_eval(Yt, K6);
            for (int i = tid; i < NE; i += NTHREADS) {
                float s = (float)(35.0 / 384.0)      * K1[i]
                        + (float)(500.0 / 1113.0)    * K3[i]
                        + (float)(125.0 / 192.0)     * K4[i]
                        + (float)(-2187.0 / 6784.0)  * K5[i]
                        + (float)(11.0 / 84.0)       * K6[i];
                Ys[i] = fmaf(dt, s, Ys[i]);
            }
            __syncthreads();
        }

        // save t = ti+1
        float* outp = out + (size_t)(ti + 1) * BATCH * DATA;
        for (int i = tid; i < M_TILE * DATA; i += NTHREADS) {
            int m = i / DATA, c = i % DATA;
            int row = base + m;
            if (row < BATCH) outp[(size_t)row * DATA + c] = Ys[m * DIM + c];
        }
    }

    if (blockIdx.x == 0 && tid == 0) {
        long long ysz = (long long)T_STEPS * BATCH * DATA;
        if (out_size > ysz) out[ysz] = (float)((T_STEPS - 1) * SUBSTEPS);
    }
}

// ---------------------------------------------------------------------------
// Weight transpose + float4 pack.
// ---------------------------------------------------------------------------
__global__ void prep_kernel(const float* __restrict__ W1,
                            const float* __restrict__ W2,
                            const float* __restrict__ W3) {
    int i = blockIdx.x * blockDim.x + threadIdx.x;
    if (i < 32 * 256) {                     // W1: [256,128] -> [32][256] float4
        int kq = i >> 8, o = i & 255;
        const float* s = W1 + o * 128 + kq * 4;
        g_W1t[i] = make_float4(s[0], s[1], s[2], s[3]);
    } else if (i < 32 * 256 + 64 * 256) {   // W2: [256,256] -> [64][256]
        int j = i - 32 * 256;
        int kq = j >> 8, o = j & 255;
        const float* s = W2 + o * 256 + kq * 4;
        g_W2t[j] = make_float4(s[0], s[1], s[2], s[3]);
    } else {                                // W3: [128,256] -> [64][128]
        int j = i - (32 * 256 + 64 * 256);
        int kq = j >> 7, o = j & 127;
        const float* s = W3 + o * 256 + kq * 4;
        g_W3t[j] = make_float4(s[0], s[1], s[2], s[3]);
    }
}

// ---------------------------------------------------------------------------
extern "C" void kernel_launch(void* const* d_in, const int* in_sizes, int n_in,
                              void* d_out, int out_size) {
    (void)in_sizes; (void)n_in;
    const float* ts = (const float*)d_in[0];
    const float* y0 = (const float*)d_in[1];
    const float* W1 = (const float*)d_in[2];
    const float* b1 = (const float*)d_in[3];
    const float* W2 = (const float*)d_in[4];
    const float* b2 = (const float*)d_in[5];
    const float* W3 = (const float*)d_in[6];
    const float* b3 = (const float*)d_in[7];
    float* out = (float*)d_out;

    prep_kernel<<<128, 256>>>(W1, W2, W3);

    const int smem_bytes = SMEM_FLOATS * (int)sizeof(float);
    cudaFuncSetAttribute(anode_main,
                         cudaFuncAttributeMaxDynamicSharedMemorySize, smem_bytes);
    anode_main<<<GRID_X, NTHREADS, smem_bytes>>>(ts, y0, b1, b2, b3, out,
                                                 out_size);
}

// round 9
// speedup vs baseline: 1.3241x; 1.0444x over previous
#include <cuda_runtime.h>

// ---------------------------------------------------------------------------
// ANODE Dopri5 solve, persistent per-block kernel. Round 9:
//   512 thr/block, 2 out-channels/thread, split-K + smem reduce.
//   NEW: rolling weight prefetch (distance 2), cross-barrier layer prefetch,
//   Dopri5 stage-combination fused into layer-3 epilogue.
// ---------------------------------------------------------------------------

#define T_STEPS  128
#define SUBSTEPS 4
#define BATCH    2048
#define DIM      128
#define WIDTH    256
#define DATA     64

#define M_TILE   14
#define GRID_X   147          // 147*14 = 2058 >= 2048
#define NTHREADS 512

typedef unsigned long long ull;

// Transposed + float4-packed weights: Wt[kq][o] = {W[o][4kq+0..3]}
__device__ float4 g_W1t[32 * 256];   // 128 KB
__device__ float4 g_W2t[64 * 256];   // 256 KB
__device__ float4 g_W3t[64 * 128];   // 128 KB

// Dopri5 tableau rows: after computing K_s, Y = Ys + dt * sum_i coef[s][i]*K_{i+1}
__constant__ float COEF[6][6] = {
    {0.2f, 0.f, 0.f, 0.f, 0.f, 0.f},
    {(float)(3.0/40.0), (float)(9.0/40.0), 0.f, 0.f, 0.f, 0.f},
    {(float)(44.0/45.0), (float)(-56.0/15.0), (float)(32.0/9.0), 0.f, 0.f, 0.f},
    {(float)(19372.0/6561.0), (float)(-25360.0/2187.0),
     (float)(64448.0/6561.0), (float)(-212.0/729.0), 0.f, 0.f},
    {(float)(9017.0/3168.0), (float)(-355.0/33.0), (float)(46732.0/5247.0),
     (float)(49.0/176.0), (float)(-5103.0/18656.0), 0.f},
    {(float)(35.0/384.0), 0.f, (float)(500.0/1113.0), (float)(125.0/192.0),
     (float)(-2187.0/6784.0), (float)(11.0/84.0)}
};

__device__ __forceinline__ void fma2(ull& d, ull a, ull b) {
    asm("fma.rn.f32x2 %0, %1, %2, %0;" : "+l"(d) : "l"(a), "l"(b));
}
__device__ __forceinline__ float hsum2(ull v) {
    float lo, hi;
    asm("mov.b64 {%0,%1}, %2;" : "=f"(lo), "=f"(hi) : "l"(v));
    return lo + hi;
}

// Shared memory layout (float offsets; all 16B aligned)
#define OFF_YS   0                    // [14][128]
#define OFF_YT   1792                 // [14][128]
#define OFF_K    3584                 // 6 x [14][128]
#define OFF_HA   14336                // [14][256]
#define OFF_HB   17920                // [14][256]
#define OFF_RED  21504                // max(4*[14][256], 8*[14][128]) = 14336
#define OFF_B1   35840
#define OFF_B2   36096
#define OFF_B3   36352
#define SMEM_FLOATS 36480             // 145920 bytes

// ---------------------------------------------------------------------------
// One Dopri5 stage: Kout = f(Yin); Ydst = Ys + dt * sum_i coef[i]*K_{i+1}
// (fused combination in layer-3 epilogue; cnt = number of K terms incl. Kout).
// ---------------------------------------------------------------------------
__device__ __noinline__ void f_core(const float* __restrict__ Yin,
                                    float* __restrict__ Kout,
                                    const float* __restrict__ coef, int cnt,
                                    float dt, float* __restrict__ Ydst) {
    extern __shared__ float sm[];
    const int tid = threadIdx.x;
    float* Ha  = sm + OFF_HA;
    float* Hb  = sm + OFF_HB;
    float* Red = sm + OFF_RED;

    const int col = tid & 127;
    const int kh  = tid >> 7;             // 0..3
    const int col3 = tid & 63;
    const int kh3  = tid >> 6;            // 0..7

    ulonglong2 p0, p1, p2, p3;            // cross-layer prefetch registers

    // =============== Layer 1: [14,128] -> [14,256], 4-way split-K =========
    {
        ull a0[M_TILE], a1[M_TILE];
#pragma unroll
        for (int m = 0; m < M_TILE; m++) { a0[m] = 0ull; a1[m] = 0ull; }
        const ulonglong2* wp = reinterpret_cast<const ulonglong2*>(g_W1t) + col;
        const int kqb = kh * 8;
        ulonglong2 c0 = wp[(kqb + 0) * 256], c1 = wp[(kqb + 0) * 256 + 128];
        ulonglong2 c2 = wp[(kqb + 1) * 256], c3 = wp[(kqb + 1) * 256 + 128];
#pragma unroll
        for (int j = 0; j < 8; j += 2) {
            ulonglong2 n0, n1, n2, n3;
            if (j + 2 < 8) {
                n0 = wp[(kqb + j + 2) * 256]; n1 = wp[(kqb + j + 2) * 256 + 128];
                n2 = wp[(kqb + j + 3) * 256]; n3 = wp[(kqb + j + 3) * 256 + 128];
            }
#pragma unroll
            for (int m = 0; m < M_TILE; m++) {
                const float* yb = Yin + m * DIM + (kqb + j) * 4;
                ulonglong2 ya = *reinterpret_cast<const ulonglong2*>(yb);
                ulonglong2 yc = *reinterpret_cast<const ulonglong2*>(yb + 4);
                fma2(a0[m], c0.x, ya.x); fma2(a0[m], c0.y, ya.y);
                fma2(a1[m], c1.x, ya.x); fma2(a1[m], c1.y, ya.y);
                fma2(a0[m], c2.x, yc.x); fma2(a0[m], c2.y, yc.y);
                fma2(a1[m], c3.x, yc.x); fma2(a1[m], c3.y, yc.y);
            }
            if (j + 2 < 8) { c0 = n0; c1 = n1; c2 = n2; c3 = n3; }
        }
        float* r = Red + kh * (M_TILE * 256) + col;
#pragma unroll
        for (int m = 0; m < M_TILE; m++) {
            r[m * 256]       = hsum2(a0[m]);
            r[m * 256 + 128] = hsum2(a1[m]);
        }
        // prefetch layer-2 first weights across the barriers
        const ulonglong2* wp2 = reinterpret_cast<const ulonglong2*>(g_W2t) + col;
        const int kqb2 = kh * 16;
        p0 = wp2[(kqb2 + 0) * 256]; p1 = wp2[(kqb2 + 0) * 256 + 128];
        p2 = wp2[(kqb2 + 1) * 256]; p3 = wp2[(kqb2 + 1) * 256 + 128];
    }
    __syncthreads();
#pragma unroll
    for (int i = 0; i < 7; i++) {
        int out = tid + NTHREADS * i;     // < 3584, idx == out ([14][256] dense)
        float v = Red[out] + Red[out + 3584] + Red[out + 7168]
                + Red[out + 10752] + sm[OFF_B1 + (out & 255)];
        Ha[out] = v > 0.f ? v : 0.f;
    }
    __syncthreads();

    // =============== Layer 2: [14,256] -> [14,256], 4-way split-K =========
    {
        ull a0[M_TILE], a1[M_TILE];
#pragma unroll
        for (int m = 0; m < M_TILE; m++) { a0[m] = 0ull; a1[m] = 0ull; }
        const ulonglong2* wp = reinterpret_cast<const ulonglong2*>(g_W2t) + col;
        const int kqb = kh * 16;
        ulonglong2 c0 = p0, c1 = p1, c2 = p2, c3 = p3;
#pragma unroll 4
        for (int j = 0; j < 16; j += 2) {
            ulonglong2 n0, n1, n2, n3;
            if (j + 2 < 16) {
                n0 = wp[(kqb + j + 2) * 256]; n1 = wp[(kqb + j + 2) * 256 + 128];
                n2 = wp[(kqb + j + 3) * 256]; n3 = wp[(kqb + j + 3) * 256 + 128];
            }
#pragma unroll
            for (int m = 0; m < M_TILE; m++) {
                const float* yb = Ha + m * WIDTH + (kqb + j) * 4;
                ulonglong2 ya = *reinterpret_cast<const ulonglong2*>(yb);
                ulonglong2 yc = *reinterpret_cast<const ulonglong2*>(yb + 4);
                fma2(a0[m], c0.x, ya.x); fma2(a0[m], c0.y, ya.y);
                fma2(a1[m], c1.x, ya.x); fma2(a1[m], c1.y, ya.y);
                fma2(a0[m], c2.x, yc.x); fma2(a0[m], c2.y, yc.y);
                fma2(a1[m], c3.x, yc.x); fma2(a1[m], c3.y, yc.y);
            }
            if (j + 2 < 16) { c0 = n0; c1 = n1; c2 = n2; c3 = n3; }
        }
        float* r = Red + kh * (M_TILE * 256) + col;
#pragma unroll
        for (int m = 0; m < M_TILE; m++) {
            r[m * 256]       = hsum2(a0[m]);
            r[m * 256 + 128] = hsum2(a1[m]);
        }
        // prefetch layer-3 first weights across the barriers
        const ulonglong2* wp3 = reinterpret_cast<const ulonglong2*>(g_W3t) + col3;
        const int kqb3 = kh3 * 8;
        p0 = wp3[(kqb3 + 0) * 128]; p1 = wp3[(kqb3 + 0) * 128 + 64];
        p2 = wp3[(kqb3 + 1) * 128]; p3 = wp3[(kqb3 + 1) * 128 + 64];
    }
    __syncthreads();
#pragma unroll
    for (int i = 0; i < 7; i++) {
        int out = tid + NTHREADS * i;
        float v = Red[out] + Red[out + 3584] + Red[out + 7168]
                + Red[out + 10752] + sm[OFF_B2 + (out & 255)];
        Hb[out] = v > 0.f ? v : 0.f;
    }
    __syncthreads();

    // =============== Layer 3: [14,256] -> [14,128], 8-way split-K =========
    {
        ull a0[M_TILE], a1[M_TILE];
#pragma unroll
        for (int m = 0; m < M_TILE; m++) { a0[m] = 0ull; a1[m] = 0ull; }
        const ulonglong2* wp = reinterpret_cast<const ulonglong2*>(g_W3t) + col3;
        const int kqb = kh3 * 8;
        ulonglong2 c0 = p0, c1 = p1, c2 = p2, c3 = p3;
#pragma unroll
        for (int j = 0; j < 8; j += 2) {
            ulonglong2 n0, n1, n2, n3;
            if (j + 2 < 8) {
                n0 = wp[(kqb + j + 2) * 128]; n1 = wp[(kqb + j + 2) * 128 + 64];
                n2 = wp[(kqb + j + 3) * 128]; n3 = wp[(kqb + j + 3) * 128 + 64];
            }
#pragma unroll
            for (int m = 0; m < M_TILE; m++) {
                const float* yb = Hb + m * WIDTH + (kqb + j) * 4;
                ulonglong2 ya = *reinterpret_cast<const ulonglong2*>(yb);
                ulonglong2 yc = *reinterpret_cast<const ulonglong2*>(yb + 4);
                fma2(a0[m], c0.x, ya.x); fma2(a0[m], c0.y, ya.y);
                fma2(a1[m], c1.x, ya.x); fma2(a1[m], c1.y, ya.y);
                fma2(a0[m], c2.x, yc.x); fma2(a0[m], c2.y, yc.y);
                fma2(a1[m], c3.x, yc.x); fma2(a1[m], c3.y, yc.y);
            }
            if (j + 2 < 8) { c0 = n0; c1 = n1; c2 = n2; c3 = n3; }
        }
        float* r = Red + kh3 * (M_TILE * 128) + col3;
#pragma unroll
        for (int m = 0; m < M_TILE; m++) {
            r[m * 128]      = hsum2(a0[m]);
            r[m * 128 + 64] = hsum2(a1[m]);
        }
    }
    __syncthreads();

    // ---- reduce + bias + FUSED Dopri5 combination ----
    for (int out = tid; out < M_TILE * DIM; out += NTHREADS) {
        float v = sm[OFF_B3 + (out & 127)];
#pragma unroll
        for (int p = 0; p < 8; p++) v += Red[out + p * 1792];
        Kout[out] = v;
        float acc = coef[cnt - 1] * v;
#pragma unroll
        for (int i = 0; i < 5; i++)
            if (i < cnt - 1) acc = fmaf(coef[i], sm[OFF_K + i * 1792 + out], acc);
        Ydst[out] = fmaf(dt, acc, sm[OFF_YS + out]);
    }
    __syncthreads();
}

// ---------------------------------------------------------------------------
__global__ __launch_bounds__(NTHREADS, 1)
void anode_main(const float* __restrict__ ts, const float* __restrict__ y0,
                const float* __restrict__ b1, const float* __restrict__ b2,
                const float* __restrict__ b3, float* __restrict__ out,
                int out_size) {
    extern __shared__ float sm[];
    const int tid  = threadIdx.x;
    const int base = blockIdx.x * M_TILE;

    float* Ys = sm + OFF_YS;
    float* Yt = sm + OFF_YT;
    float* Kb = sm + OFF_K;

    if (tid < 256) { sm[OFF_B1 + tid] = b1[tid]; sm[OFF_B2 + tid] = b2[tid]; }
    if (tid < 128) sm[OFF_B3 + tid] = b3[tid];

    for (int i = tid; i < M_TILE * DIM; i += NTHREADS) {
        int m = i >> 7, d = i & 127;
        int row = base + m;
        Ys[i] = (row < BATCH) ? y0[(size_t)row * DIM + d] : 0.f;
    }
    __syncthreads();

    // save t = 0
    for (int i = tid; i < M_TILE * DATA; i += NTHREADS) {
        int m = i / DATA, c = i % DATA;
        int row = base + m;
        if (row < BATCH) out[(size_t)row * DATA + c] = Ys[m * DIM + c];
    }

    for (int ti = 0; ti < T_STEPS - 1; ti++) {
        const float dt = (ts[ti + 1] - ts[ti]) * (1.0f / SUBSTEPS);

        for (int sub = 0; sub < SUBSTEPS; sub++) {
            f_core(Ys, Kb,            COEF[0], 1, dt, Yt);
            f_core(Yt, Kb + 1792,     COEF[1], 2, dt, Yt);
            f_core(Yt, Kb + 2 * 1792, COEF[2], 3, dt, Yt);
            f_core(Yt, Kb + 3 * 1792, COEF[3], 4, dt, Yt);
            f_core(Yt, Kb + 4 * 1792, COEF[4], 5, dt, Yt);
            f_core(Yt, Kb + 5 * 1792, COEF[5], 6, dt, Ys);
        }

        // save t = ti+1
        float* outp = out + (size_t)(ti + 1) * BATCH * DATA;
        for (int i = tid; i < M_TILE * DATA; i += NTHREADS) {
            int m = i / DATA, c = i % DATA;
            int row = base + m;
            if (row < BATCH) outp[(size_t)row * DATA + c] = Ys[m * DIM + c];
        }
    }

    if (blockIdx.x == 0 && tid == 0) {
        long long ysz = (long long)T_STEPS * BATCH * DATA;
        if (out_size > ysz) out[ysz] = (float)((T_STEPS - 1) * SUBSTEPS);
    }
}

// ---------------------------------------------------------------------------
// Weight transpose + float4 pack.
// ---------------------------------------------------------------------------
__global__ void prep_kernel(const float* __restrict__ W1,
                            const float* __restrict__ W2,
                            const float* __restrict__ W3) {
    int i = blockIdx.x * blockDim.x + threadIdx.x;
    if (i < 32 * 256) {                     // W1: [256,128] -> [32][256] float4
        int kq = i >> 8, o = i & 255;
        const float* s = W1 + o * 128 + kq * 4;
        g_W1t[i] = make_float4(s[0], s[1], s[2], s[3]);
    } else if (i < 32 * 256 + 64 * 256) {   // W2: [256,256] -> [64][256]
        int j = i - 32 * 256;
        int kq = j >> 8, o = j & 255;
        const float* s = W2 + o * 256 + kq * 4;
        g_W2t[j] = make_float4(s[0], s[1], s[2], s[3]);
    } else {                                // W3: [128,256] -> [64][128]
        int j = i - (32 * 256 + 64 * 256);
        int kq = j >> 7, o = j & 127;
        const float* s = W3 + o * 256 + kq * 4;
        g_W3t[j] = make_float4(s[0], s[1], s[2], s[3]);
    }
}

// ---------------------------------------------------------------------------
extern "C" void kernel_launch(void* const* d_in, const int* in_sizes, int n_in,
                              void* d_out, int out_size) {
    (void)in_sizes; (void)n_in;
    const float* ts = (const float*)d_in[0];
    const float* y0 = (const float*)d_in[1];
    const float* W1 = (const float*)d_in[2];
    const float* b1 = (const float*)d_in[3];
    const float* W2 = (const float*)d_in[4];
    const float* b2 = (const float*)d_in[5];
    const float* W3 = (const float*)d_in[6];
    const float* b3 = (const float*)d_in[7];
    float* out = (float*)d_out;

    prep_kernel<<<128, 256>>>(W1, W2, W3);

    const int smem_bytes = SMEM_FLOATS * (int)sizeof(float);
    cudaFuncSetAttribute(anode_main,
                         cudaFuncAttributeMaxDynamicSharedMemorySize, smem_bytes);
    anode_main<<<GRID_X, NTHREADS, smem_bytes>>>(ts, y0, b1, b2, b3, out,
                                                 out_size);
}